// round 7
// baseline (speedup 1.0000x reference)
#include <cuda_runtime.h>
#include <math.h>

#define FULLMASK 0xffffffffu

constexpr int B_ROWS = 262144;
constexpr int IN_DIM = 96;
constexpr int R = 4;

__device__ __forceinline__ unsigned long long ffma2(unsigned long long a,
                                                    unsigned long long b,
                                                    unsigned long long c) {
    unsigned long long d;
    asm("fma.rn.f32x2 %0, %1, %2, %3;" : "=l"(d) : "l"(a), "l"(b), "l"(c));
    return d;
}

__device__ __forceinline__ unsigned long long pack2(unsigned lo, unsigned hi) {
    unsigned long long d;
    asm("mov.b64 %0, {%1, %2};" : "=l"(d) : "r"(lo), "r"(hi));
    return d;
}

__device__ __forceinline__ float tanh_fast(float x) {
    float y;
    asm("tanh.approx.f32 %0, %1;" : "=f"(y) : "f"(x));
    return y;
}

__global__ void __launch_bounds__(128, 3)
actor_fused_kernel(
    const float* __restrict__ s_input,
    const float* __restrict__ en_W1,  const float* __restrict__ en_b1,
    const float* __restrict__ en_W2,  const float* __restrict__ en_b2,
    const float* __restrict__ oa_W1,  const float* __restrict__ oa_b1,
    const float* __restrict__ oa_W2,  const float* __restrict__ oa_b2,
    const float* __restrict__ goal_W1,const float* __restrict__ goal_b1,
    const float* __restrict__ goal_W2,const float* __restrict__ goal_b2,
    const float* __restrict__ oa_ln_g,const float* __restrict__ oa_ln_b,
    const float* __restrict__ goal_ln_g,const float* __restrict__ goal_ln_b,
    const float* __restrict__ act_W1, const float* __restrict__ act_b1,
    const float* __restrict__ act_W2, const float* __restrict__ act_b2,
    const float* __restrict__ act_W3, const float* __restrict__ act_b3,
    float* __restrict__ out)
{
    // encoder groups: 0 = oa (lanes 0-14), 1 = en/self (lane 15), 2 = goal (lanes 16-31)
    __shared__ __align__(16) float sW1T[3 * 32 * 4];
    __shared__ __align__(16) float sB1 [3 * 32];
    __shared__ __align__(16) float sW2 [3 * 32 * 16];
    __shared__ __align__(16) float sB2 [3 * 16];
    __shared__ float sLN_g[32], sLN_b[32];
    __shared__ __align__(16) float sAW1T[32 * 52];
    __shared__ __align__(16) float sAW2T[32 * 36];
    __shared__ float sAB1[32], sAB2[32], sAW3[64], sAB3[2];
    // per-warp scratch, per-row slots:
    //  [0,64)    so[r]; [64,192) pools[r] (0-15 oa, 16-31 food); [192,320) hv[r]
    __shared__ __align__(16) float sScr[4][320];

    const int t = threadIdx.x;
    for (int idx = t; idx < 3 * 32 * 4; idx += blockDim.x) {
        int gg = idx >> 7, r = idx & 127, j = r >> 2, i = r & 3;
        float v;
        if (gg == 0)      v = oa_W1[i * 32 + j];
        else if (gg == 1) v = en_W1[i * 32 + j];
        else              v = (i < 2) ? goal_W1[i * 32 + j] : 0.f;
        sW1T[idx] = v;
    }
    for (int idx = t; idx < 96; idx += blockDim.x) {
        int gg = idx >> 5, j = idx & 31;
        sB1[idx] = (gg == 0 ? oa_b1 : gg == 1 ? en_b1 : goal_b1)[j];
    }
    for (int idx = t; idx < 3 * 512; idx += blockDim.x) {
        int gg = idx >> 9, r = idx & 511;
        sW2[idx] = (gg == 0 ? oa_W2 : gg == 1 ? en_W2 : goal_W2)[r];
    }
    for (int idx = t; idx < 48; idx += blockDim.x) {
        int gg = idx >> 4, j = idx & 15;
        sB2[idx] = (gg == 0 ? oa_b2 : gg == 1 ? en_b2 : goal_b2)[j];
    }
    if (t < 16) {
        sLN_g[t]      = oa_ln_g[t];   sLN_b[t]      = oa_ln_b[t];
        sLN_g[16 + t] = goal_ln_g[t]; sLN_b[16 + t] = goal_ln_b[t];
    }
    for (int idx = t; idx < 32 * 48; idx += blockDim.x) {
        int l = idx / 48, d = idx % 48;
        sAW1T[l * 52 + d] = act_W1[d * 32 + l];
    }
    for (int idx = t; idx < 32 * 32; idx += blockDim.x) {
        int l = idx >> 5, j = idx & 31;
        sAW2T[l * 36 + j] = act_W2[j * 32 + l];
    }
    if (t < 32) { sAB1[t] = act_b1[t]; sAB2[t] = act_b2[t]; }
    if (t < 64) sAW3[t] = act_W3[t];
    if (t < 2)  sAB3[t] = act_b3[t];
    __syncthreads();

    const int lane  = t & 31;
    const int q16   = lane & 15;
    const int gwarp = (blockIdx.x * blockDim.x + t) >> 5;
    const int nwarp = (gridDim.x * blockDim.x) >> 5;

    const int g = (lane < 15) ? 0 : ((lane == 15) ? 1 : 2);
    const float4* w1p = reinterpret_cast<const float4*>(sW1T + g * 128);
    const float4* b1q = reinterpret_cast<const float4*>(sB1 + g * 32);
    const uint4*  w2q = reinterpret_cast<const uint4*>(sW2 + g * 512);   // 4 x LDS.128 per j-row
    const uint4*  b2q = reinterpret_cast<const uint4*>(sB2 + g * 16);

    float* scr = sScr[t >> 5];

    const float4* aw1t = reinterpret_cast<const float4*>(sAW1T + lane * 52);
    const float4* aw2t = reinterpret_cast<const float4*>(sAW2T + lane * 36);
    const float lnG = sLN_g[lane], lnB = sLN_b[lane];
    const float aB1 = sAB1[lane],  aB2 = sAB2[lane];
    const float w3a = sAW3[lane * 2 + 0], w3b = sAW3[lane * 2 + 1];
    const float b3a = sAB3[0], b3b = sAB3[1];
    const bool lo16 = (lane < 16);
    const bool lo8  = (q16 & 8) == 0;

    for (int row0 = gwarp * R; row0 < B_ROWS; row0 += nwarp * R) {
        // ---- per-lane item inputs for R rows ----
        float x0[R], x1[R], x2[R], x3[R];
        #pragma unroll
        for (int r = 0; r < R; r++) {
            const float* rb = s_input + (size_t)(row0 + r) * IN_DIM;
            if (lane < 15) {
                float2 a = *reinterpret_cast<const float2*>(rb + 4 + 2 * lane);
                float2 b = *reinterpret_cast<const float2*>(rb + 34 + 2 * lane);
                x0[r] = a.x; x1[r] = a.y; x2[r] = b.x; x3[r] = b.y;
            } else if (lane == 15) {
                float4 v = *reinterpret_cast<const float4*>(rb);
                x0[r] = v.x; x1[r] = v.y; x2[r] = v.z; x3[r] = v.w;
            } else {
                float2 v = *reinterpret_cast<const float2*>(rb + 64 + 2 * (lane - 16));
                x0[r] = v.x; x1[r] = v.y; x2[r] = 0.f; x3[r] = 0.f;
            }
        }

        // ---- encoder MLP for R rows ----
        unsigned long long acc[R][8];
        {
            uint4 bA = b2q[0], bB = b2q[1], bC = b2q[2], bD = b2q[3];
            #pragma unroll
            for (int r = 0; r < R; r++) {
                acc[r][0] = pack2(bA.x, bA.y); acc[r][1] = pack2(bA.z, bA.w);
                acc[r][2] = pack2(bB.x, bB.y); acc[r][3] = pack2(bB.z, bB.w);
                acc[r][4] = pack2(bC.x, bC.y); acc[r][5] = pack2(bC.z, bC.w);
                acc[r][6] = pack2(bD.x, bD.y); acc[r][7] = pack2(bD.z, bD.w);
            }
        }

        #pragma unroll
        for (int jq = 0; jq < 8; jq++) {
            float4 b4 = b1q[jq];
            #pragma unroll
            for (int jj = 0; jj < 4; jj++) {
                const int j = 4 * jq + jj;
                float4 w = w1p[j];
                float bj = (jj == 0) ? b4.x : (jj == 1) ? b4.y : (jj == 2) ? b4.z : b4.w;
                // w2 row: 64B = 4 x LDS.128
                uint4 wA = w2q[j * 4 + 0], wB = w2q[j * 4 + 1];
                uint4 wC = w2q[j * 4 + 2], wD = w2q[j * 4 + 3];
                unsigned long long w2r[8];
                w2r[0] = pack2(wA.x, wA.y); w2r[1] = pack2(wA.z, wA.w);
                w2r[2] = pack2(wB.x, wB.y); w2r[3] = pack2(wB.z, wB.w);
                w2r[4] = pack2(wC.x, wC.y); w2r[5] = pack2(wC.z, wC.w);
                w2r[6] = pack2(wD.x, wD.y); w2r[7] = pack2(wD.z, wD.w);
                #pragma unroll
                for (int r = 0; r < R; r++) {
                    float hj = bj;
                    hj = fmaf(x0[r], w.x, hj); hj = fmaf(x1[r], w.y, hj);
                    hj = fmaf(x2[r], w.z, hj); hj = fmaf(x3[r], w.w, hj);
                    hj = fmaxf(hj, 0.f);
                    unsigned hb = __float_as_uint(hj);
                    unsigned long long hh = pack2(hb, hb);
                    #pragma unroll
                    for (int qq = 0; qq < 8; qq++) acc[r][qq] = ffma2(hh, w2r[qq], acc[r][qq]);
                }
            }
        }

        // ---- attention phase: per row, publish so + pools ----
        #pragma unroll
        for (int r = 0; r < R; r++) {
            float e[16];
            #pragma unroll
            for (int qq = 0; qq < 8; qq++) {
                unsigned lo, hi;
                asm("mov.b64 {%0, %1}, %2;" : "=r"(lo), "=r"(hi) : "l"(acc[r][qq]));
                e[2 * qq]     = fmaxf(__uint_as_float(lo), 0.f);
                e[2 * qq + 1] = fmaxf(__uint_as_float(hi), 0.f);
            }

            if (lane == 15) {
                float4* sw = reinterpret_cast<float4*>(scr + 16 * r);
                sw[0] = make_float4(e[0],  e[1],  e[2],  e[3]);
                sw[1] = make_float4(e[4],  e[5],  e[6],  e[7]);
                sw[2] = make_float4(e[8],  e[9],  e[10], e[11]);
                sw[3] = make_float4(e[12], e[13], e[14], e[15]);
            }
            __syncwarp();

            const float4* soqr = reinterpret_cast<const float4*>(scr + 16 * r);
            float sc = 0.f;
            #pragma unroll
            for (int qq = 0; qq < 4; qq++) {
                float4 s4 = soqr[qq];
                sc = fmaf(s4.x, e[4 * qq + 0], sc);
                sc = fmaf(s4.y, e[4 * qq + 1], sc);
                sc = fmaf(s4.z, e[4 * qq + 2], sc);
                sc = fmaf(s4.w, e[4 * qq + 3], sc);
            }
            sc *= 0.25f;
            const bool active = (lane != 15);
            float p = active ? __expf(sc) : 0.f;
            float ps = p;
            #pragma unroll
            for (int o = 1; o < 16; o <<= 1) ps += __shfl_xor_sync(FULLMASK, ps, o);
            const float aw = p / ps;

            // reduce-scatter of aw*e over 16-lane half -> pooled[q16]
            float A8[8];
            {
                const bool hb = (q16 & 8) != 0;
                #pragma unroll
                for (int i = 0; i < 8; i++) {
                    float kp = hb ? e[i + 8] : e[i];
                    float sd = hb ? e[i]     : e[i + 8];
                    A8[i] = fmaf(aw, kp, __shfl_xor_sync(FULLMASK, aw * sd, 8));
                }
            }
            float A4[4];
            {
                const bool hb = (q16 & 4) != 0;
                #pragma unroll
                for (int i = 0; i < 4; i++) {
                    float kp = hb ? A8[i + 4] : A8[i];
                    float sd = hb ? A8[i]     : A8[i + 4];
                    A4[i] = kp + __shfl_xor_sync(FULLMASK, sd, 4);
                }
            }
            float A2[2];
            {
                const bool hb = (q16 & 2) != 0;
                #pragma unroll
                for (int i = 0; i < 2; i++) {
                    float kp = hb ? A4[i + 2] : A4[i];
                    float sd = hb ? A4[i]     : A4[i + 2];
                    A2[i] = kp + __shfl_xor_sync(FULLMASK, sd, 2);
                }
            }
            float pooled;
            {
                const bool hb = (q16 & 1) != 0;
                float kp = hb ? A2[1] : A2[0];
                float sd = hb ? A2[0] : A2[1];
                pooled = kp + __shfl_xor_sync(FULLMASK, sd, 1);
            }

            // LayerNorm: fused (sum, sumsq) butterfly
            {
                float a = pooled, b = pooled * pooled;
                float s = (lo8 ? a : b) + __shfl_xor_sync(FULLMASK, lo8 ? b : a, 8);
                s += __shfl_xor_sync(FULLMASK, s, 4);
                s += __shfl_xor_sync(FULLMASK, s, 2);
                s += __shfl_xor_sync(FULLMASK, s, 1);
                float o8 = __shfl_xor_sync(FULLMASK, s, 8);
                float suma = lo8 ? s : o8;
                float sumb = lo8 ? o8 : s;
                const float mu  = suma * (1.f / 16.f);
                const float var = fmaf(sumb, 1.f / 16.f, -mu * mu);
                const float inv = rsqrtf(var + 1e-5f);
                const float myn = fmaxf(fmaf((pooled - mu) * inv, lnG, lnB), 0.f);
                scr[64 + 32 * r + lane] = myn;
            }
        }
        __syncwarp();

        // ---- head phase, batched over R rows ----
        float hv[R];
        #pragma unroll
        for (int r = 0; r < R; r++) hv[r] = aB1;

        #pragma unroll
        for (int dq = 0; dq < 4; dq++) {              // self part
            float4 w = aw1t[dq];
            #pragma unroll
            for (int r = 0; r < R; r++) {
                float4 s4 = *reinterpret_cast<const float4*>(scr + 16 * r + 4 * dq);
                hv[r] = fmaf(s4.x, w.x, hv[r]); hv[r] = fmaf(s4.y, w.y, hv[r]);
                hv[r] = fmaf(s4.z, w.z, hv[r]); hv[r] = fmaf(s4.w, w.w, hv[r]);
            }
        }
        #pragma unroll
        for (int dq = 0; dq < 4; dq++) {              // food pool part
            float4 w = aw1t[4 + dq];
            #pragma unroll
            for (int r = 0; r < R; r++) {
                float4 f4 = *reinterpret_cast<const float4*>(scr + 64 + 32 * r + 16 + 4 * dq);
                hv[r] = fmaf(f4.x, w.x, hv[r]); hv[r] = fmaf(f4.y, w.y, hv[r]);
                hv[r] = fmaf(f4.z, w.z, hv[r]); hv[r] = fmaf(f4.w, w.w, hv[r]);
            }
        }
        #pragma unroll
        for (int dq = 0; dq < 4; dq++) {              // other pool part
            float4 w = aw1t[8 + dq];
            #pragma unroll
            for (int r = 0; r < R; r++) {
                float4 o4 = *reinterpret_cast<const float4*>(scr + 64 + 32 * r + 4 * dq);
                hv[r] = fmaf(o4.x, w.x, hv[r]); hv[r] = fmaf(o4.y, w.y, hv[r]);
                hv[r] = fmaf(o4.z, w.z, hv[r]); hv[r] = fmaf(o4.w, w.w, hv[r]);
            }
        }
        #pragma unroll
        for (int r = 0; r < R; r++) {
            hv[r] = fmaxf(hv[r], 0.01f * hv[r]);
            scr[192 + 32 * r + lane] = hv[r];
        }
        __syncwarp();

        float h2[R];
        #pragma unroll
        for (int r = 0; r < R; r++) h2[r] = aB2;
        #pragma unroll
        for (int jq = 0; jq < 8; jq++) {
            float4 w = aw2t[jq];
            #pragma unroll
            for (int r = 0; r < R; r++) {
                float4 v4 = *reinterpret_cast<const float4*>(scr + 192 + 32 * r + 4 * jq);
                h2[r] = fmaf(v4.x, w.x, h2[r]); h2[r] = fmaf(v4.y, w.y, h2[r]);
                h2[r] = fmaf(v4.z, w.z, h2[r]); h2[r] = fmaf(v4.w, w.w, h2[r]);
            }
        }

        #pragma unroll
        for (int r = 0; r < R; r++) {
            float hh = fmaxf(h2[r], 0.01f * h2[r]);
            float a = hh * w3a, b = hh * w3b;
            float s = (lo16 ? a : b) + __shfl_xor_sync(FULLMASK, lo16 ? b : a, 16);
            s += __shfl_xor_sync(FULLMASK, s, 8);
            s += __shfl_xor_sync(FULLMASK, s, 4);
            s += __shfl_xor_sync(FULLMASK, s, 2);
            s += __shfl_xor_sync(FULLMASK, s, 1);
            float s16 = __shfl_sync(FULLMASK, s, 16);
            if (lane == 0) {
                float2 rr;
                rr.x = tanh_fast(s + b3a);
                rr.y = tanh_fast(s16 + b3b);
                *reinterpret_cast<float2*>(out + (size_t)(row0 + r) * 2) = rr;
            }
        }
    }
}

extern "C" void kernel_launch(void* const* d_in, const int* in_sizes, int n_in,
                              void* d_out, int out_size) {
    (void)in_sizes; (void)n_in; (void)out_size;
    dim3 grid(444), block(128);
    actor_fused_kernel<<<grid, block>>>(
        (const float*)d_in[0],
        (const float*)d_in[1],  (const float*)d_in[2],
        (const float*)d_in[3],  (const float*)d_in[4],
        (const float*)d_in[5],  (const float*)d_in[6],
        (const float*)d_in[7],  (const float*)d_in[8],
        (const float*)d_in[9],  (const float*)d_in[10],
        (const float*)d_in[11], (const float*)d_in[12],
        (const float*)d_in[13], (const float*)d_in[14],
        (const float*)d_in[15], (const float*)d_in[16],
        (const float*)d_in[17], (const float*)d_in[18],
        (const float*)d_in[19], (const float*)d_in[20],
        (const float*)d_in[21], (const float*)d_in[22],
        (float*)d_out);
}

// round 8
// speedup vs baseline: 1.0039x; 1.0039x over previous
#include <cuda_runtime.h>
#include <math.h>

#define FULLMASK 0xffffffffu

constexpr int B_ROWS = 262144;
constexpr int IN_DIM = 96;
constexpr int R = 4;

__device__ __forceinline__ unsigned long long ffma2(unsigned long long a,
                                                    unsigned long long b,
                                                    unsigned long long c) {
    unsigned long long d;
    asm("fma.rn.f32x2 %0, %1, %2, %3;" : "=l"(d) : "l"(a), "l"(b), "l"(c));
    return d;
}

__device__ __forceinline__ unsigned long long pack2(unsigned lo, unsigned hi) {
    unsigned long long d;
    asm("mov.b64 %0, {%1, %2};" : "=l"(d) : "r"(lo), "r"(hi));
    return d;
}

__device__ __forceinline__ float tanh_fast(float x) {
    float y;
    asm("tanh.approx.f32 %0, %1;" : "=f"(y) : "f"(x));
    return y;
}

__global__ void __launch_bounds__(128, 3)
actor_fused_kernel(
    const float* __restrict__ s_input,
    const float* __restrict__ en_W1,  const float* __restrict__ en_b1,
    const float* __restrict__ en_W2,  const float* __restrict__ en_b2,
    const float* __restrict__ oa_W1,  const float* __restrict__ oa_b1,
    const float* __restrict__ oa_W2,  const float* __restrict__ oa_b2,
    const float* __restrict__ goal_W1,const float* __restrict__ goal_b1,
    const float* __restrict__ goal_W2,const float* __restrict__ goal_b2,
    const float* __restrict__ oa_ln_g,const float* __restrict__ oa_ln_b,
    const float* __restrict__ goal_ln_g,const float* __restrict__ goal_ln_b,
    const float* __restrict__ act_W1, const float* __restrict__ act_b1,
    const float* __restrict__ act_W2, const float* __restrict__ act_b2,
    const float* __restrict__ act_W3, const float* __restrict__ act_b3,
    float* __restrict__ out)
{
    // encoder groups: 0 = oa (lanes 0-14), 1 = en/self (lane 15), 2 = goal (lanes 16-31)
    __shared__ __align__(16) float sW1T[3 * 32 * 4];
    __shared__ __align__(16) float sB1 [3 * 32];
    __shared__ __align__(16) float sW2 [3 * 32 * 16];
    __shared__ __align__(16) float sB2 [3 * 16];
    __shared__ float sLN_g[32], sLN_b[32];
    __shared__ __align__(16) float sAW1T[32 * 52];
    __shared__ __align__(16) float sAW2T[32 * 36];
    __shared__ float sAB1[32], sAB2[32], sAW3[64], sAB3[2];
    // per-warp scratch, per-row slots:
    //  [0,64)    so[r]; [64,192) pools[r] (0-15 oa, 16-31 food); [192,320) hv[r]
    __shared__ __align__(16) float sScr[4][320];

    const int t = threadIdx.x;
    for (int idx = t; idx < 3 * 32 * 4; idx += blockDim.x) {
        int gg = idx >> 7, r = idx & 127, j = r >> 2, i = r & 3;
        float v;
        if (gg == 0)      v = oa_W1[i * 32 + j];
        else if (gg == 1) v = en_W1[i * 32 + j];
        else              v = (i < 2) ? goal_W1[i * 32 + j] : 0.f;
        sW1T[idx] = v;
    }
    for (int idx = t; idx < 96; idx += blockDim.x) {
        int gg = idx >> 5, j = idx & 31;
        sB1[idx] = (gg == 0 ? oa_b1 : gg == 1 ? en_b1 : goal_b1)[j];
    }
    for (int idx = t; idx < 3 * 512; idx += blockDim.x) {
        int gg = idx >> 9, r = idx & 511;
        sW2[idx] = (gg == 0 ? oa_W2 : gg == 1 ? en_W2 : goal_W2)[r];
    }
    for (int idx = t; idx < 48; idx += blockDim.x) {
        int gg = idx >> 4, j = idx & 15;
        sB2[idx] = (gg == 0 ? oa_b2 : gg == 1 ? en_b2 : goal_b2)[j];
    }
    if (t < 16) {
        sLN_g[t]      = oa_ln_g[t];   sLN_b[t]      = oa_ln_b[t];
        sLN_g[16 + t] = goal_ln_g[t]; sLN_b[16 + t] = goal_ln_b[t];
    }
    for (int idx = t; idx < 32 * 48; idx += blockDim.x) {
        int l = idx / 48, d = idx % 48;
        sAW1T[l * 52 + d] = act_W1[d * 32 + l];
    }
    for (int idx = t; idx < 32 * 32; idx += blockDim.x) {
        int l = idx >> 5, j = idx & 31;
        sAW2T[l * 36 + j] = act_W2[j * 32 + l];
    }
    if (t < 32) { sAB1[t] = act_b1[t]; sAB2[t] = act_b2[t]; }
    if (t < 64) sAW3[t] = act_W3[t];
    if (t < 2)  sAB3[t] = act_b3[t];
    __syncthreads();

    const int lane  = t & 31;
    const int q16   = lane & 15;
    const int gwarp = (blockIdx.x * blockDim.x + t) >> 5;
    const int nwarp = (gridDim.x * blockDim.x) >> 5;

    const int g = (lane < 15) ? 0 : ((lane == 15) ? 1 : 2);
    const float4* w1p = reinterpret_cast<const float4*>(sW1T + g * 128);
    const float4* b1q = reinterpret_cast<const float4*>(sB1 + g * 32);
    const uint4*  w2q = reinterpret_cast<const uint4*>(sW2 + g * 512);   // 4 x LDS.128 per j-row
    const uint4*  b2q = reinterpret_cast<const uint4*>(sB2 + g * 16);

    float* scr = sScr[t >> 5];

    const float4* aw1t = reinterpret_cast<const float4*>(sAW1T + lane * 52);
    const float4* aw2t = reinterpret_cast<const float4*>(sAW2T + lane * 36);
    const float lnG = sLN_g[lane], lnB = sLN_b[lane];
    const float aB1 = sAB1[lane],  aB2 = sAB2[lane];
    const float w3a = sAW3[lane * 2 + 0], w3b = sAW3[lane * 2 + 1];
    const float b3a = sAB3[0], b3b = sAB3[1];
    const bool lo16 = (lane < 16);
    const bool lo8  = (q16 & 8) == 0;

    for (int row0 = gwarp * R; row0 < B_ROWS; row0 += nwarp * R) {
        // ---- per-lane item inputs for R rows ----
        float x0[R], x1[R], x2[R], x3[R];
        #pragma unroll
        for (int r = 0; r < R; r++) {
            const float* rb = s_input + (size_t)(row0 + r) * IN_DIM;
            if (lane < 15) {
                float2 a = *reinterpret_cast<const float2*>(rb + 4 + 2 * lane);
                float2 b = *reinterpret_cast<const float2*>(rb + 34 + 2 * lane);
                x0[r] = a.x; x1[r] = a.y; x2[r] = b.x; x3[r] = b.y;
            } else if (lane == 15) {
                float4 v = *reinterpret_cast<const float4*>(rb);
                x0[r] = v.x; x1[r] = v.y; x2[r] = v.z; x3[r] = v.w;
            } else {
                float2 v = *reinterpret_cast<const float2*>(rb + 64 + 2 * (lane - 16));
                x0[r] = v.x; x1[r] = v.y; x2[r] = 0.f; x3[r] = 0.f;
            }
        }

        // ---- encoder MLP for R rows ----
        unsigned long long acc[R][8];
        {
            uint4 bA = b2q[0], bB = b2q[1], bC = b2q[2], bD = b2q[3];
            #pragma unroll
            for (int r = 0; r < R; r++) {
                acc[r][0] = pack2(bA.x, bA.y); acc[r][1] = pack2(bA.z, bA.w);
                acc[r][2] = pack2(bB.x, bB.y); acc[r][3] = pack2(bB.z, bB.w);
                acc[r][4] = pack2(bC.x, bC.y); acc[r][5] = pack2(bC.z, bC.w);
                acc[r][6] = pack2(bD.x, bD.y); acc[r][7] = pack2(bD.z, bD.w);
            }
        }

        #pragma unroll
        for (int jq = 0; jq < 8; jq++) {
            float4 b4 = b1q[jq];
            #pragma unroll
            for (int jj = 0; jj < 4; jj++) {
                const int j = 4 * jq + jj;
                float4 w = w1p[j];
                float bj = (jj == 0) ? b4.x : (jj == 1) ? b4.y : (jj == 2) ? b4.z : b4.w;
                // w2 row: 64B = 4 x LDS.128
                uint4 wA = w2q[j * 4 + 0], wB = w2q[j * 4 + 1];
                uint4 wC = w2q[j * 4 + 2], wD = w2q[j * 4 + 3];
                unsigned long long w2r[8];
                w2r[0] = pack2(wA.x, wA.y); w2r[1] = pack2(wA.z, wA.w);
                w2r[2] = pack2(wB.x, wB.y); w2r[3] = pack2(wB.z, wB.w);
                w2r[4] = pack2(wC.x, wC.y); w2r[5] = pack2(wC.z, wC.w);
                w2r[6] = pack2(wD.x, wD.y); w2r[7] = pack2(wD.z, wD.w);
                #pragma unroll
                for (int r = 0; r < R; r++) {
                    float hj = bj;
                    hj = fmaf(x0[r], w.x, hj); hj = fmaf(x1[r], w.y, hj);
                    hj = fmaf(x2[r], w.z, hj); hj = fmaf(x3[r], w.w, hj);
                    hj = fmaxf(hj, 0.f);
                    unsigned hb = __float_as_uint(hj);
                    unsigned long long hh = pack2(hb, hb);
                    #pragma unroll
                    for (int qq = 0; qq < 8; qq++) acc[r][qq] = ffma2(hh, w2r[qq], acc[r][qq]);
                }
            }
        }

        // ---- attention phase: per row, publish so + pools ----
        #pragma unroll
        for (int r = 0; r < R; r++) {
            float e[16];
            #pragma unroll
            for (int qq = 0; qq < 8; qq++) {
                unsigned lo, hi;
                asm("mov.b64 {%0, %1}, %2;" : "=r"(lo), "=r"(hi) : "l"(acc[r][qq]));
                e[2 * qq]     = fmaxf(__uint_as_float(lo), 0.f);
                e[2 * qq + 1] = fmaxf(__uint_as_float(hi), 0.f);
            }

            if (lane == 15) {
                float4* sw = reinterpret_cast<float4*>(scr + 16 * r);
                sw[0] = make_float4(e[0],  e[1],  e[2],  e[3]);
                sw[1] = make_float4(e[4],  e[5],  e[6],  e[7]);
                sw[2] = make_float4(e[8],  e[9],  e[10], e[11]);
                sw[3] = make_float4(e[12], e[13], e[14], e[15]);
            }
            __syncwarp();

            const float4* soqr = reinterpret_cast<const float4*>(scr + 16 * r);
            float sc = 0.f;
            #pragma unroll
            for (int qq = 0; qq < 4; qq++) {
                float4 s4 = soqr[qq];
                sc = fmaf(s4.x, e[4 * qq + 0], sc);
                sc = fmaf(s4.y, e[4 * qq + 1], sc);
                sc = fmaf(s4.z, e[4 * qq + 2], sc);
                sc = fmaf(s4.w, e[4 * qq + 3], sc);
            }
            sc *= 0.25f;
            const bool active = (lane != 15);
            float p = active ? __expf(sc) : 0.f;
            float ps = p;
            #pragma unroll
            for (int o = 1; o < 16; o <<= 1) ps += __shfl_xor_sync(FULLMASK, ps, o);
            const float aw = p / ps;

            // reduce-scatter of aw*e over 16-lane half -> pooled[q16]
            float A8[8];
            {
                const bool hb = (q16 & 8) != 0;
                #pragma unroll
                for (int i = 0; i < 8; i++) {
                    float kp = hb ? e[i + 8] : e[i];
                    float sd = hb ? e[i]     : e[i + 8];
                    A8[i] = fmaf(aw, kp, __shfl_xor_sync(FULLMASK, aw * sd, 8));
                }
            }
            float A4[4];
            {
                const bool hb = (q16 & 4) != 0;
                #pragma unroll
                for (int i = 0; i < 4; i++) {
                    float kp = hb ? A8[i + 4] : A8[i];
                    float sd = hb ? A8[i]     : A8[i + 4];
                    A4[i] = kp + __shfl_xor_sync(FULLMASK, sd, 4);
                }
            }
            float A2[2];
            {
                const bool hb = (q16 & 2) != 0;
                #pragma unroll
                for (int i = 0; i < 2; i++) {
                    float kp = hb ? A4[i + 2] : A4[i];
                    float sd = hb ? A4[i]     : A4[i + 2];
                    A2[i] = kp + __shfl_xor_sync(FULLMASK, sd, 2);
                }
            }
            float pooled;
            {
                const bool hb = (q16 & 1) != 0;
                float kp = hb ? A2[1] : A2[0];
                float sd = hb ? A2[0] : A2[1];
                pooled = kp + __shfl_xor_sync(FULLMASK, sd, 1);
            }

            // LayerNorm: fused (sum, sumsq) butterfly
            {
                float a = pooled, b = pooled * pooled;
                float s = (lo8 ? a : b) + __shfl_xor_sync(FULLMASK, lo8 ? b : a, 8);
                s += __shfl_xor_sync(FULLMASK, s, 4);
                s += __shfl_xor_sync(FULLMASK, s, 2);
                s += __shfl_xor_sync(FULLMASK, s, 1);
                float o8 = __shfl_xor_sync(FULLMASK, s, 8);
                float suma = lo8 ? s : o8;
                float sumb = lo8 ? o8 : s;
                const float mu  = suma * (1.f / 16.f);
                const float var = fmaf(sumb, 1.f / 16.f, -mu * mu);
                const float inv = rsqrtf(var + 1e-5f);
                const float myn = fmaxf(fmaf((pooled - mu) * inv, lnG, lnB), 0.f);
                scr[64 + 32 * r + lane] = myn;
            }
        }
        __syncwarp();

        // ---- head phase, batched over R rows ----
        float hv[R];
        #pragma unroll
        for (int r = 0; r < R; r++) hv[r] = aB1;

        #pragma unroll
        for (int dq = 0; dq < 4; dq++) {              // self part
            float4 w = aw1t[dq];
            #pragma unroll
            for (int r = 0; r < R; r++) {
                float4 s4 = *reinterpret_cast<const float4*>(scr + 16 * r + 4 * dq);
                hv[r] = fmaf(s4.x, w.x, hv[r]); hv[r] = fmaf(s4.y, w.y, hv[r]);
                hv[r] = fmaf(s4.z, w.z, hv[r]); hv[r] = fmaf(s4.w, w.w, hv[r]);
            }
        }
        #pragma unroll
        for (int dq = 0; dq < 4; dq++) {              // food pool part
            float4 w = aw1t[4 + dq];
            #pragma unroll
            for (int r = 0; r < R; r++) {
                float4 f4 = *reinterpret_cast<const float4*>(scr + 64 + 32 * r + 16 + 4 * dq);
                hv[r] = fmaf(f4.x, w.x, hv[r]); hv[r] = fmaf(f4.y, w.y, hv[r]);
                hv[r] = fmaf(f4.z, w.z, hv[r]); hv[r] = fmaf(f4.w, w.w, hv[r]);
            }
        }
        #pragma unroll
        for (int dq = 0; dq < 4; dq++) {              // other pool part
            float4 w = aw1t[8 + dq];
            #pragma unroll
            for (int r = 0; r < R; r++) {
                float4 o4 = *reinterpret_cast<const float4*>(scr + 64 + 32 * r + 4 * dq);
                hv[r] = fmaf(o4.x, w.x, hv[r]); hv[r] = fmaf(o4.y, w.y, hv[r]);
                hv[r] = fmaf(o4.z, w.z, hv[r]); hv[r] = fmaf(o4.w, w.w, hv[r]);
            }
        }
        #pragma unroll
        for (int r = 0; r < R; r++) {
            hv[r] = fmaxf(hv[r], 0.01f * hv[r]);
            scr[192 + 32 * r + lane] = hv[r];
        }
        __syncwarp();

        float h2[R];
        #pragma unroll
        for (int r = 0; r < R; r++) h2[r] = aB2;
        #pragma unroll
        for (int jq = 0; jq < 8; jq++) {
            float4 w = aw2t[jq];
            #pragma unroll
            for (int r = 0; r < R; r++) {
                float4 v4 = *reinterpret_cast<const float4*>(scr + 192 + 32 * r + 4 * jq);
                h2[r] = fmaf(v4.x, w.x, h2[r]); h2[r] = fmaf(v4.y, w.y, h2[r]);
                h2[r] = fmaf(v4.z, w.z, h2[r]); h2[r] = fmaf(v4.w, w.w, h2[r]);
            }
        }

        #pragma unroll
        for (int r = 0; r < R; r++) {
            float hh = fmaxf(h2[r], 0.01f * h2[r]);
            float a = hh * w3a, b = hh * w3b;
            float s = (lo16 ? a : b) + __shfl_xor_sync(FULLMASK, lo16 ? b : a, 16);
            s += __shfl_xor_sync(FULLMASK, s, 8);
            s += __shfl_xor_sync(FULLMASK, s, 4);
            s += __shfl_xor_sync(FULLMASK, s, 2);
            s += __shfl_xor_sync(FULLMASK, s, 1);
            float s16 = __shfl_sync(FULLMASK, s, 16);
            if (lane == 0) {
                float2 rr;
                rr.x = tanh_fast(s + b3a);
                rr.y = tanh_fast(s16 + b3b);
                *reinterpret_cast<float2*>(out + (size_t)(row0 + r) * 2) = rr;
            }
        }
    }
}

extern "C" void kernel_launch(void* const* d_in, const int* in_sizes, int n_in,
                              void* d_out, int out_size) {
    (void)in_sizes; (void)n_in; (void)out_size;
    dim3 grid(444), block(128);
    actor_fused_kernel<<<grid, block>>>(
        (const float*)d_in[0],
        (const float*)d_in[1],  (const float*)d_in[2],
        (const float*)d_in[3],  (const float*)d_in[4],
        (const float*)d_in[5],  (const float*)d_in[6],
        (const float*)d_in[7],  (const float*)d_in[8],
        (const float*)d_in[9],  (const float*)d_in[10],
        (const float*)d_in[11], (const float*)d_in[12],
        (const float*)d_in[13], (const float*)d_in[14],
        (const float*)d_in[15], (const float*)d_in[16],
        (const float*)d_in[17], (const float*)d_in[18],
        (const float*)d_in[19], (const float*)d_in[20],
        (const float*)d_in[21], (const float*)d_in[22],
        (float*)d_out);
}